// round 9
// baseline (speedup 1.0000x reference)
#include <cuda_runtime.h>
#include <math_constants.h>

#define BH      16
#define LQ      4096
#define DD      64
#define SK      45
#define UU      45
#define NSPLIT  32
#define SPLIT_KEYS 128
#define NCHUNK  32
#define CHUNK   128

// inversion config
#define NCH     5          // key chunks per bh
#define CHR     824        // rows per chunk (last = 800)
#define QSPLIT  2
#define DSMEM_BYTES (CHR * DD * 4)   // 210944

// ---------------- scratch (device globals; no allocation allowed) ----------
__device__ __align__(16) float g_M[BH * LQ];
__device__ __align__(16) float g_pmx[BH * NCH * LQ];
__device__ __align__(16) float g_psm[BH * NCH * LQ];
__device__ __align__(16) int   g_top[BH * UU];
__device__ __align__(16) float g_pm[BH * UU * NSPLIT];
__device__ __align__(16) float g_pl[BH * UU * NSPLIT];
__device__ __align__(16) float g_pacc[BH * UU * NSPLIT * DD];
__device__ __align__(16) float g_chunk[BH * NCHUNK * DD];

// ---------------- Stage 1a: inverted sparsity measure ----------------------
// Block = (chunk, bh, qsplit). K chunk resident in dynamic smem; each warp
// walks 128 queries, ballot-compacts the in-chunk samples, dots from smem.
__global__ __launch_bounds__(512) void k_Minv(const float* __restrict__ Q,
                                              const float* __restrict__ K,
                                              const int*   __restrict__ idx)
{
    extern __shared__ __align__(16) float ks[];       // [crows][64]
    __shared__ int scr[16][48];

    int ch = blockIdx.x, bh = blockIdx.y, qs = blockIdx.z;
    int c0 = ch * CHR;
    int crows = min(CHR, LQ - c0);
    int tid = threadIdx.x, w = tid >> 5, lane = tid & 31;
    int r = lane >> 3, cslot = lane & 7;

    // stream chunk into smem (coalesced float4)
    {
        const float4* Kc = (const float4*)(K + ((size_t)bh * LQ + c0) * DD);
        float4* ks4 = (float4*)ks;
        for (int i = tid; i < crows * 16; i += 512) ks4[i] = __ldg(Kc + i);
    }
    __syncthreads();

    const float* pmxb = g_pmx + (size_t)(bh * NCH + ch) * LQ;
    const float* psmb = g_psm + (size_t)(bh * NCH + ch) * LQ;
    (void)pmxb; (void)psmb;

    for (int i = 0; i < 128; i++) {
        int q = qs * (LQ / QSPLIT) + i * 16 + w;

        int e0 = __ldg(idx + q * SK + lane);
        int e1 = (lane < SK - 32) ? __ldg(idx + q * SK + 32 + lane) : -1;
        bool in0 = (e0 >= c0) && (e0 < c0 + crows);
        bool in1 = (lane < SK - 32) && (e1 >= c0) && (e1 < c0 + crows);
        unsigned m0 = __ballot_sync(0xffffffffu, in0);
        unsigned m1 = __ballot_sync(0xffffffffu, in1);
        int cnt = __popc(m0) + __popc(m1);

        if (in0) scr[w][__popc(m0 & ((1u << lane) - 1u))] = e0 - c0;
        if (in1) scr[w][__popc(m0) + __popc(m1 & ((1u << lane) - 1u))] = e1 - c0;
        __syncwarp();

        float mx = -CUDART_INF_F, sm = 0.f;
        if (cnt > 0) {
            const float4* Qr4 = (const float4*)(Q + ((size_t)bh * LQ + q) * DD);
            float4 qa = __ldg(Qr4 + cslot);
            float4 qb = __ldg(Qr4 + cslot + 8);
            int steps = (cnt + 3) >> 2;
            for (int tt = 0; tt < steps; tt++) {
                int s = 4 * tt + r;
                int row = scr[w][(s < cnt) ? s : 0];
                const float4* kp = ((const float4*)ks) + row * 16;
                float4 ka = kp[cslot], kb = kp[cslot + 8];
                float d;
                d = ka.x * qa.x;
                d = fmaf(ka.y, qa.y, d);
                d = fmaf(ka.z, qa.z, d);
                d = fmaf(ka.w, qa.w, d);
                d = fmaf(kb.x, qb.x, d);
                d = fmaf(kb.y, qb.y, d);
                d = fmaf(kb.z, qb.z, d);
                d = fmaf(kb.w, qb.w, d);
                d += __shfl_xor_sync(0xffffffffu, d, 1);
                d += __shfl_xor_sync(0xffffffffu, d, 2);
                d += __shfl_xor_sync(0xffffffffu, d, 4);
                if (s < cnt) { mx = fmaxf(mx, d); sm += d; }
            }
            mx = fmaxf(mx, __shfl_xor_sync(0xffffffffu, mx, 8));
            sm +=          __shfl_xor_sync(0xffffffffu, sm, 8);
            mx = fmaxf(mx, __shfl_xor_sync(0xffffffffu, mx, 16));
            sm +=          __shfl_xor_sync(0xffffffffu, sm, 16);
        }
        if (lane == 0) {
            g_pmx[(size_t)(bh * NCH + ch) * LQ + q] = mx;
            g_psm[(size_t)(bh * NCH + ch) * LQ + q] = sm;
        }
        __syncwarp();
    }
}

// ---------------- Stage 1b: combine chunk partials into M ------------------
__global__ __launch_bounds__(256) void k_Mcomb()
{
    int gq = blockIdx.x * 256 + threadIdx.x;     // bh*LQ + q
    int bh = gq >> 12, q = gq & (LQ - 1);
    float mx = -CUDART_INF_F, sm = 0.f;
#pragma unroll
    for (int c = 0; c < NCH; c++) {
        mx = fmaxf(mx, g_pmx[(size_t)(bh * NCH + c) * LQ + q]);
        sm +=          g_psm[(size_t)(bh * NCH + c) * LQ + q];
    }
    g_M[gq] = mx - sm * (1.0f / (float)LQ);
}

// ---------------- Stage 2: top-45 per (b,h), index-sorted ------------------
__global__ __launch_bounds__(256) void k_top()
{
    __shared__ unsigned long long ckeys[16 * UU];
    __shared__ int stop[UU];
    int bh = blockIdx.x, t = threadIdx.x, w = t >> 5, lane = t & 31;
    int h = lane >> 4, sl = lane & 15;
    int list = 2 * w + h;
    int base = w * 512 + h * 256 + sl;

    unsigned long long k[16];
#pragma unroll
    for (int kk = 0; kk < 16; kk++) {
        int i = base + 16 * kk;
        unsigned int u = __float_as_uint(g_M[bh * LQ + i]);
        u ^= (unsigned int)(((int)u >> 31)) | 0x80000000u;
        k[kk] = ((unsigned long long)u << 32) | (unsigned long long)(0xFFFFFFFFu - (unsigned int)i);
    }

    for (int it = 0; it < UU; it++) {
        unsigned long long b = k[0];
#pragma unroll
        for (int kk = 1; kk < 16; kk++) b = (k[kk] > b) ? k[kk] : b;
#pragma unroll
        for (int off = 8; off > 0; off >>= 1) {
            unsigned long long o = __shfl_xor_sync(0xffffffffu, b, off);
            b = (o > b) ? o : b;
        }
        if (sl == 0) ckeys[list * UU + it] = b;
#pragma unroll
        for (int kk = 0; kk < 16; kk++) if (k[kk] == b) k[kk] = 0ull;
    }
    __syncthreads();

    for (int x = t; x < 16 * UU; x += 256) {
        unsigned long long Kx = ckeys[x];
        int rank = 0;
#pragma unroll
        for (int L = 0; L < 16; L++) {
            const unsigned long long* a = &ckeys[L * UU];
            int lo = 0, hi = UU;
            while (lo < hi) {
                int mid = (lo + hi) >> 1;
                if (a[mid] > Kx) lo = mid + 1; else hi = mid;
            }
            rank += lo;
        }
        if (rank < UU)
            stop[rank] = (int)(0xFFFFFFFFu - (unsigned int)(Kx & 0xFFFFFFFFull));
    }
    __syncthreads();

    if (t < UU) {
        int my = stop[t], cnt = 0;
#pragma unroll 9
        for (int j = 0; j < UU; j++) cnt += (stop[j] < my);
        g_top[bh * UU + cnt] = my;
    }
}

// ---------------- Stage 3: split-KV flash attention for selected rows ------
__global__ __launch_bounds__(256) void k_attn(const float* __restrict__ Q,
                                              const float* __restrict__ K,
                                              const float* __restrict__ V)
{
    __shared__ __align__(16) float Qs[48][DD];
    __shared__ __align__(16) float Kt[DD][66];
    __shared__ __align__(16) float Vs[64][DD];
    __shared__ int tops[UU];

    int split = blockIdx.x, bh = blockIdx.y;
    int t = threadIdx.x, w = t >> 5, lane = t & 31;
    int band = (w < 4) ? w : 11 - w;

    if (t < UU) tops[t] = g_top[bh * UU + t];
    __syncthreads();
    const float scale = 0.125f;
    for (int r = w; r < UU; r += 8) {
        float2 v = *(const float2*)(Q + ((size_t)bh * LQ + tops[r]) * DD + 2 * lane);
        Qs[r][2 * lane]     = v.x * scale;
        Qs[r][2 * lane + 1] = v.y * scale;
    }
    int s_maxtop = 0;
    float mx[6], l[6]; float2 acc[6];
#pragma unroll
    for (int j = 0; j < 6; j++) { mx[j] = -CUDART_INF_F; l[j] = 0.f; acc[j] = make_float2(0.f, 0.f); }
    __syncthreads();
    s_maxtop = tops[UU - 1];

    int k0 = split * SPLIT_KEYS;
    for (int sub = 0; sub < SPLIT_KEYS / 64; sub++) {
        int kb = k0 + sub * 64;
        __syncthreads();
        if (kb > s_maxtop) break;
        for (int i = t; i < 64 * DD; i += 256) {
            int kk = i >> 6, d = i & 63;
            Kt[d][kk] = K[((size_t)bh * LQ + kb + kk) * DD + d];
            Vs[kk][d] = V[((size_t)bh * LQ + kb + kk) * DD + d];
        }
        __syncthreads();

        bool act[6]; bool any = false;
#pragma unroll
        for (int j = 0; j < 6; j++) {
            int u = 6 * band + j;
            act[j] = (u < UU) && (kb <= tops[u]);
            any |= act[j];
        }
        if (!any) continue;

        float s0[6], s1[6];
#pragma unroll
        for (int j = 0; j < 6; j++) { s0[j] = 0.f; s1[j] = 0.f; }
#pragma unroll 16
        for (int d = 0; d < DD; d++) {
            float2 kt = *(const float2*)&Kt[d][2 * lane];
#pragma unroll
            for (int j = 0; j < 6; j++) {
                if (act[j]) {
                    float qv = Qs[6 * band + j][d];
                    s0[j] = fmaf(qv, kt.x, s0[j]);
                    s1[j] = fmaf(qv, kt.y, s1[j]);
                }
            }
        }

        float2 e2[6];
        int kk0 = kb + 2 * lane;
#pragma unroll
        for (int j = 0; j < 6; j++) {
            e2[j] = make_float2(0.f, 0.f);
            if (!act[j]) continue;
            int mu = tops[6 * band + j];
            float a = (kk0     <= mu) ? s0[j] : -CUDART_INF_F;
            float b = (kk0 + 1 <= mu) ? s1[j] : -CUDART_INF_F;
            float lm = fmaxf(a, b);
#pragma unroll
            for (int o = 16; o > 0; o >>= 1) lm = fmaxf(lm, __shfl_xor_sync(0xffffffffu, lm, o));
            float nm   = fmaxf(mx[j], lm);
            float corr = __expf(mx[j] - nm);
            float ea = __expf(a - nm);
            float eb = __expf(b - nm);
            float ts = ea + eb;
#pragma unroll
            for (int o = 16; o > 0; o >>= 1) ts += __shfl_xor_sync(0xffffffffu, ts, o);
            mx[j] = nm;
            l[j]  = l[j] * corr + ts;
            acc[j].x *= corr; acc[j].y *= corr;
            e2[j].x = ea; e2[j].y = eb;
        }

#pragma unroll 8
        for (int kk = 0; kk < 64; kk++) {
            float2 vv = *(const float2*)&Vs[kk][2 * lane];
#pragma unroll
            for (int j = 0; j < 6; j++) {
                if (act[j]) {
                    float ek = __shfl_sync(0xffffffffu, (kk & 1) ? e2[j].y : e2[j].x, kk >> 1);
                    acc[j].x = fmaf(ek, vv.x, acc[j].x);
                    acc[j].y = fmaf(ek, vv.y, acc[j].y);
                }
            }
        }
    }

#pragma unroll
    for (int j = 0; j < 6; j++) {
        int u = 6 * band + j;
        if (u >= UU) continue;
        int pb = (bh * UU + u) * NSPLIT + split;
        *(float2*)&g_pacc[(size_t)pb * DD + 2 * lane] = acc[j];
        if (lane == 0) { g_pm[pb] = mx[j]; g_pl[pb] = l[j]; }
    }
}

// ---------------- combine split partials into selected rows ----------------
__global__ __launch_bounds__(64) void k_comb(float* __restrict__ out)
{
    int g  = blockIdx.x;                    // bh*UU + u
    int bh = g / UU;
    int d  = threadIdx.x;
    float mg = -CUDART_INF_F;
#pragma unroll 4
    for (int i = 0; i < NSPLIT; i++) mg = fmaxf(mg, g_pm[g * NSPLIT + i]);
    float os = 0.f, ls = 0.f;
    for (int i = 0; i < NSPLIT; i++) {
        float wgt = __expf(g_pm[g * NSPLIT + i] - mg);
        ls = fmaf(wgt, g_pl[g * NSPLIT + i], ls);
        os = fmaf(wgt, g_pacc[(size_t)(g * NSPLIT + i) * DD + d], os);
    }
    int row = g_top[g];
    out[((size_t)bh * LQ + row) * DD + d] = os / ls;
}

// ---------------- cumsum(V): chunk sums (vectorized) -----------------------
__global__ __launch_bounds__(512) void k_csumA(const float* __restrict__ V)
{
    __shared__ __align__(16) float4 sred[32][16];   // 8 KB
    int c = blockIdx.x, bh = blockIdx.y;
    int t = threadIdx.x, r = t >> 4, c4 = t & 15;
    const float4* base = (const float4*)(V + ((size_t)bh * LQ + c * CHUNK) * DD);
    float4 a = __ldg(base + (size_t)r        * 16 + c4);
    float4 b = __ldg(base + (size_t)(r + 32) * 16 + c4);
    float4 d = __ldg(base + (size_t)(r + 64) * 16 + c4);
    float4 e = __ldg(base + (size_t)(r + 96) * 16 + c4);
    float4 s;
    s.x = (a.x + b.x) + (d.x + e.x);
    s.y = (a.y + b.y) + (d.y + e.y);
    s.z = (a.z + b.z) + (d.z + e.z);
    s.w = (a.w + b.w) + (d.w + e.w);
    sred[r][c4] = s;
    __syncthreads();
    if (t < 128) {
        int rr = t >> 4;
        float4 p0 = sred[rr][c4],      p1 = sred[rr + 8][c4];
        float4 p2 = sred[rr + 16][c4], p3 = sred[rr + 24][c4];
        float4 q;
        q.x = (p0.x + p1.x) + (p2.x + p3.x);
        q.y = (p0.y + p1.y) + (p2.y + p3.y);
        q.z = (p0.z + p1.z) + (p2.z + p3.z);
        q.w = (p0.w + p1.w) + (p2.w + p3.w);
        sred[rr][c4] = q;
    }
    __syncthreads();
    if (t < 16) {
        float4 q0 = sred[0][t], q1 = sred[1][t], q2 = sred[2][t], q3 = sred[3][t];
        float4 q4 = sred[4][t], q5 = sred[5][t], q6 = sred[6][t], q7 = sred[7][t];
        float4 q;
        q.x = ((q0.x + q1.x) + (q2.x + q3.x)) + ((q4.x + q5.x) + (q6.x + q7.x));
        q.y = ((q0.y + q1.y) + (q2.y + q3.y)) + ((q4.y + q5.y) + (q6.y + q7.y));
        q.z = ((q0.z + q1.z) + (q2.z + q3.z)) + ((q4.z + q5.z) + (q6.z + q7.z));
        q.w = ((q0.w + q1.w) + (q2.w + q3.w)) + ((q4.w + q5.w) + (q6.w + q7.w));
        ((float4*)(g_chunk + (bh * NCHUNK + c) * DD))[t] = q;
    }
}

// ---------------- cumsum(V): per-chunk scan, register-resident -------------
__global__ __launch_bounds__(512) void k_csumC(const float* __restrict__ V,
                                               float* __restrict__ out)
{
    __shared__ float gsum[8][64];
    int c = blockIdx.x, bh = blockIdx.y;
    int t = threadIdx.x, g = t >> 6, d = t & 63;

    float pre = 0.f;
    for (int j = 0; j < c; j++) pre += g_chunk[(bh * NCHUNK + j) * DD + d];

    const float* base = V + ((size_t)bh * LQ + c * CHUNK + g * 16) * DD + d;
    float v[16];
#pragma unroll
    for (int i = 0; i < 16; i++) v[i] = base[i * DD];
#pragma unroll
    for (int i = 1; i < 16; i++) v[i] += v[i - 1];
    gsum[g][d] = v[15];
    __syncthreads();
    float off = pre;
#pragma unroll
    for (int j = 0; j < 7; j++) if (j < g) off += gsum[j][d];
    float* ob = out + ((size_t)bh * LQ + c * CHUNK + g * 16) * DD + d;
#pragma unroll
    for (int i = 0; i < 16; i++) ob[i * DD] = v[i] + off;
}

// ---------------- launcher --------------------------------------------------
extern "C" void kernel_launch(void* const* d_in, const int* in_sizes, int n_in,
                              void* d_out, int out_size)
{
    (void)in_sizes; (void)n_in; (void)out_size;
    const float* Q   = (const float*)d_in[0];
    const float* K   = (const float*)d_in[1];
    const float* V   = (const float*)d_in[2];
    const int*   idx = (const int*)d_in[3];
    float* out = (float*)d_out;

    // opt-in to >48KB dynamic smem (idempotent, immediate API — capture-safe)
    cudaFuncSetAttribute(k_Minv, cudaFuncAttributeMaxDynamicSharedMemorySize,
                         DSMEM_BYTES);

    k_Minv<<<dim3(NCH, BH, QSPLIT), 512, DSMEM_BYTES>>>(Q, K, idx);
    k_Mcomb<<<BH * LQ / 256, 256>>>();
    k_top<<<BH, 256>>>();
    k_attn<<<dim3(NSPLIT, BH), 256>>>(Q, K, V);
    k_csumA<<<dim3(NCHUNK, BH), 512>>>(V);
    k_csumC<<<dim3(NCHUNK, BH), 512>>>(V, out);
    k_comb<<<BH * UU, 64>>>(out);
}

// round 10
// speedup vs baseline: 2.0728x; 2.0728x over previous
#include <cuda_runtime.h>
#include <math_constants.h>

#define BH      16
#define LQ      4096
#define DD      64
#define SK      45
#define UU      45
#define NSPLIT  32
#define SPLIT_KEYS 128
#define NCHUNK  32
#define CHUNK   128

// ---------------- scratch (device globals; no allocation allowed) ----------
__device__ __align__(16) float g_M[BH * LQ];
__device__ __align__(16) int   g_top[BH * UU];
__device__ __align__(16) float g_pm[BH * UU * NSPLIT];
__device__ __align__(16) float g_pl[BH * UU * NSPLIT];
__device__ __align__(16) float g_pacc[BH * UU * NSPLIT * DD];
__device__ __align__(16) float g_chunk[BH * NCHUNK * DD];

// ---------------- Stage 1: sparsity measure M (round-8 pipelined) ----------
__global__ __launch_bounds__(256) void k_M(const float* __restrict__ Q,
                                           const float* __restrict__ K,
                                           const int*   __restrict__ idx)
{
    __shared__ int sidx[8][48];
    int w = threadIdx.x >> 5, lane = threadIdx.x & 31;
    int gw = blockIdx.x * 8 + w;
    int bh = gw >> 12, q = gw & (LQ - 1);
    const float4* Kb4 = (const float4*)(K + (size_t)bh * (LQ * DD));

    sidx[w][lane] = idx[q * SK + lane];
    if (lane < SK - 32) sidx[w][32 + lane] = idx[q * SK + 32 + lane];
    if (lane >= 29)     sidx[w][16 + lane] = idx[q * SK + SK - 1];  // pad 45..47
    __syncwarp();

    int r = lane >> 3, c = lane & 7;
    const float4* Qr4 = (const float4*)(Q + ((size_t)bh * LQ + q) * DD);
    float4 qa = Qr4[c];
    float4 qb = Qr4[c + 8];

    float4 A0[4], B0[4], A1[4], B1[4];
    float mx = -CUDART_INF_F, sm = 0.f;

#pragma unroll
    for (int i = 0; i < 4; i++) {
        const float4* kp = Kb4 + (size_t)sidx[w][4 * i + r] * 16;
        A0[i] = __ldg(kp + c); B0[i] = __ldg(kp + c + 8);
    }
#pragma unroll
    for (int i = 0; i < 4; i++) {
        const float4* kp = Kb4 + (size_t)sidx[w][16 + 4 * i + r] * 16;
        A1[i] = __ldg(kp + c); B1[i] = __ldg(kp + c + 8);
    }

#pragma unroll
    for (int blk = 0; blk < 3; blk++) {
#pragma unroll
        for (int i = 0; i < 4; i++) {
            float4 ka = A0[i], kb = B0[i];
            float d;
            d = ka.x * qa.x;
            d = fmaf(ka.y, qa.y, d);
            d = fmaf(ka.z, qa.z, d);
            d = fmaf(ka.w, qa.w, d);
            d = fmaf(kb.x, qb.x, d);
            d = fmaf(kb.y, qb.y, d);
            d = fmaf(kb.z, qb.z, d);
            d = fmaf(kb.w, qb.w, d);
            d += __shfl_xor_sync(0xffffffffu, d, 1);
            d += __shfl_xor_sync(0xffffffffu, d, 2);
            d += __shfl_xor_sync(0xffffffffu, d, 4);
            int samp = 16 * blk + 4 * i + r;
            if (samp < SK) { mx = fmaxf(mx, d); sm += d; }
        }
#pragma unroll
        for (int i = 0; i < 4; i++) { A0[i] = A1[i]; B0[i] = B1[i]; }
        if (blk == 0) {
#pragma unroll
            for (int i = 0; i < 4; i++) {
                const float4* kp = Kb4 + (size_t)sidx[w][32 + 4 * i + r] * 16;
                A1[i] = __ldg(kp + c); B1[i] = __ldg(kp + c + 8);
            }
        }
    }

    mx = fmaxf(mx, __shfl_xor_sync(0xffffffffu, mx, 8));
    sm +=          __shfl_xor_sync(0xffffffffu, sm, 8);
    mx = fmaxf(mx, __shfl_xor_sync(0xffffffffu, mx, 16));
    sm +=          __shfl_xor_sync(0xffffffffu, sm, 16);
    if (lane == 0) g_M[gw] = mx - sm * (1.0f / (float)LQ);
}

// ---------------- Stage 2: top-45 per (b,h), index-sorted ------------------
__global__ __launch_bounds__(256) void k_top()
{
    __shared__ unsigned long long ckeys[16 * UU];
    __shared__ int stop[UU];
    int bh = blockIdx.x, t = threadIdx.x, w = t >> 5, lane = t & 31;
    int h = lane >> 4, sl = lane & 15;
    int list = 2 * w + h;
    int base = w * 512 + h * 256 + sl;

    unsigned long long k[16];
#pragma unroll
    for (int kk = 0; kk < 16; kk++) {
        int i = base + 16 * kk;
        unsigned int u = __float_as_uint(g_M[bh * LQ + i]);
        u ^= (unsigned int)(((int)u >> 31)) | 0x80000000u;
        k[kk] = ((unsigned long long)u << 32) | (unsigned long long)(0xFFFFFFFFu - (unsigned int)i);
    }

    for (int it = 0; it < UU; it++) {
        unsigned long long b = k[0];
#pragma unroll
        for (int kk = 1; kk < 16; kk++) b = (k[kk] > b) ? k[kk] : b;
#pragma unroll
        for (int off = 8; off > 0; off >>= 1) {
            unsigned long long o = __shfl_xor_sync(0xffffffffu, b, off);
            b = (o > b) ? o : b;
        }
        if (sl == 0) ckeys[list * UU + it] = b;
#pragma unroll
        for (int kk = 0; kk < 16; kk++) if (k[kk] == b) k[kk] = 0ull;
    }
    __syncthreads();

    for (int x = t; x < 16 * UU; x += 256) {
        unsigned long long Kx = ckeys[x];
        int rank = 0;
#pragma unroll
        for (int L = 0; L < 16; L++) {
            const unsigned long long* a = &ckeys[L * UU];
            int lo = 0, hi = UU;
            while (lo < hi) {
                int mid = (lo + hi) >> 1;
                if (a[mid] > Kx) lo = mid + 1; else hi = mid;
            }
            rank += lo;
        }
        if (rank < UU)
            stop[rank] = (int)(0xFFFFFFFFu - (unsigned int)(Kx & 0xFFFFFFFFull));
    }
    __syncthreads();

    if (t < UU) {
        int my = stop[t], cnt = 0;
#pragma unroll 9
        for (int j = 0; j < UU; j++) cnt += (stop[j] < my);
        g_top[bh * UU + cnt] = my;
    }
}

// ---------------- Stage 3: split-KV flash attention (optimized) ------------
// KP buffer: Kt[64][66] during score phase, reused as P[48][68] for weights.
#define KT(d, kk) KP[(d) * 66 + (kk)]
#define PW(u, kk) KP[(u) * 68 + (kk)]

__global__ __launch_bounds__(256) void k_attn(const float* __restrict__ Q,
                                              const float* __restrict__ K,
                                              const float* __restrict__ V)
{
    __shared__ __align__(16) float Qs[48][DD];     // 12.3 KB (pre-scaled)
    __shared__ __align__(16) float KP[DD * 66];    // 16.9 KB (Kt / P union)
    __shared__ __align__(16) float Vs[64][DD];     // 16.4 KB
    __shared__ int tops[UU];

    int split = blockIdx.x, bh = blockIdx.y;
    int t = threadIdx.x, w = t >> 5, lane = t & 31;
    int band = (w < 4) ? w : 11 - w;

    if (t < UU) tops[t] = g_top[bh * UU + t];
    __syncthreads();
    const float scale = 0.125f;
    for (int r = w; r < UU; r += 8) {
        float2 v = *(const float2*)(Q + ((size_t)bh * LQ + tops[r]) * DD + 2 * lane);
        Qs[r][2 * lane]     = v.x * scale;
        Qs[r][2 * lane + 1] = v.y * scale;
    }
    float mx[6], l[6]; float2 acc[6];
#pragma unroll
    for (int j = 0; j < 6; j++) { mx[j] = -CUDART_INF_F; l[j] = 0.f; acc[j] = make_float2(0.f, 0.f); }
    __syncthreads();
    int s_maxtop = tops[UU - 1];

    int k0 = split * SPLIT_KEYS;
    for (int sub = 0; sub < SPLIT_KEYS / 64; sub++) {
        int kb = k0 + sub * 64;
        __syncthreads();                      // prev AV readers done (P/Vs)
        if (kb > s_maxtop) break;

        // vectorized tile load: 4 float4 per thread per array
        {
            const float4* Kc = (const float4*)(K + ((size_t)bh * LQ + kb) * DD);
            const float4* Vc = (const float4*)(V + ((size_t)bh * LQ + kb) * DD);
#pragma unroll
            for (int rep = 0; rep < 4; rep++) {
                int idx4 = t + 256 * rep;          // 0..1023
                int kk = idx4 >> 4, c4 = idx4 & 15;
                float4 kv = __ldg(Kc + idx4);
                KT(4 * c4 + 0, kk) = kv.x;
                KT(4 * c4 + 1, kk) = kv.y;
                KT(4 * c4 + 2, kk) = kv.z;
                KT(4 * c4 + 3, kk) = kv.w;
                *(float4*)&Vs[kk][4 * c4] = __ldg(Vc + idx4);
            }
        }
        __syncthreads();

        bool act[6]; bool any = false;
#pragma unroll
        for (int j = 0; j < 6; j++) {
            int u = 6 * band + j;
            act[j] = (u < UU) && (kb <= tops[u]);
            any |= act[j];
        }

        float e0[6], e1[6];
        if (any) {
            float s0[6], s1[6];
#pragma unroll
            for (int j = 0; j < 6; j++) { s0[j] = 0.f; s1[j] = 0.f; }
#pragma unroll
            for (int d4 = 0; d4 < DD; d4 += 4) {
                float2 kt0 = *(const float2*)&KT(d4 + 0, 2 * lane);
                float2 kt1 = *(const float2*)&KT(d4 + 1, 2 * lane);
                float2 kt2 = *(const float2*)&KT(d4 + 2, 2 * lane);
                float2 kt3 = *(const float2*)&KT(d4 + 3, 2 * lane);
#pragma unroll
                for (int j = 0; j < 6; j++) {
                    if (act[j]) {
                        float4 qv = *(const float4*)&Qs[6 * band + j][d4];
                        s0[j] = fmaf(qv.x, kt0.x, s0[j]);
                        s0[j] = fmaf(qv.y, kt1.x, s0[j]);
                        s0[j] = fmaf(qv.z, kt2.x, s0[j]);
                        s0[j] = fmaf(qv.w, kt3.x, s0[j]);
                        s1[j] = fmaf(qv.x, kt0.y, s1[j]);
                        s1[j] = fmaf(qv.y, kt1.y, s1[j]);
                        s1[j] = fmaf(qv.z, kt2.y, s1[j]);
                        s1[j] = fmaf(qv.w, kt3.y, s1[j]);
                    }
                }
            }

            int kk0 = kb + 2 * lane;
#pragma unroll
            for (int j = 0; j < 6; j++) {
                e0[j] = 0.f; e1[j] = 0.f;
                if (!act[j]) continue;        // warp-uniform
                int mu = tops[6 * band + j];
                float a = (kk0     <= mu) ? s0[j] : -CUDART_INF_F;
                float b = (kk0 + 1 <= mu) ? s1[j] : -CUDART_INF_F;
                float lm = fmaxf(a, b);
#pragma unroll
                for (int o = 16; o > 0; o >>= 1) lm = fmaxf(lm, __shfl_xor_sync(0xffffffffu, lm, o));
                float nm   = fmaxf(mx[j], lm);
                float corr = __expf(mx[j] - nm);
                float ea = __expf(a - nm);
                float eb = __expf(b - nm);
                float ts = ea + eb;
#pragma unroll
                for (int o = 16; o > 0; o >>= 1) ts += __shfl_xor_sync(0xffffffffu, ts, o);
                mx[j] = nm;
                l[j]  = l[j] * corr + ts;
                acc[j].x *= corr; acc[j].y *= corr;
                e0[j] = ea; e1[j] = eb;
            }
        }

        __syncthreads();                      // all Kt reads done
        if (any) {
#pragma unroll
            for (int j = 0; j < 6; j++) {
                if (act[j]) {                 // warp-uniform
                    *(float2*)&PW(6 * band + j, 2 * lane) = make_float2(e0[j], e1[j]);
                }
            }
        }
        __syncthreads();                      // P visible

        if (any) {
#pragma unroll
            for (int kk4 = 0; kk4 < 64; kk4 += 4) {
                float2 vv0 = *(const float2*)&Vs[kk4 + 0][2 * lane];
                float2 vv1 = *(const float2*)&Vs[kk4 + 1][2 * lane];
                float2 vv2 = *(const float2*)&Vs[kk4 + 2][2 * lane];
                float2 vv3 = *(const float2*)&Vs[kk4 + 3][2 * lane];
#pragma unroll
                for (int j = 0; j < 6; j++) {
                    if (act[j]) {
                        float4 p = *(const float4*)&PW(6 * band + j, kk4);
                        acc[j].x = fmaf(p.x, vv0.x, acc[j].x);
                        acc[j].x = fmaf(p.y, vv1.x, acc[j].x);
                        acc[j].x = fmaf(p.z, vv2.x, acc[j].x);
                        acc[j].x = fmaf(p.w, vv3.x, acc[j].x);
                        acc[j].y = fmaf(p.x, vv0.y, acc[j].y);
                        acc[j].y = fmaf(p.y, vv1.y, acc[j].y);
                        acc[j].y = fmaf(p.z, vv2.y, acc[j].y);
                        acc[j].y = fmaf(p.w, vv3.y, acc[j].y);
                    }
                }
            }
        }
    }

#pragma unroll
    for (int j = 0; j < 6; j++) {
        int u = 6 * band + j;
        if (u >= UU) continue;
        int pb = (bh * UU + u) * NSPLIT + split;
        *(float2*)&g_pacc[(size_t)pb * DD + 2 * lane] = acc[j];
        if (lane == 0) { g_pm[pb] = mx[j]; g_pl[pb] = l[j]; }
    }
}

// ---------------- combine split partials into selected rows ----------------
__global__ __launch_bounds__(64) void k_comb(float* __restrict__ out)
{
    int g  = blockIdx.x;                    // bh*UU + u
    int bh = g / UU;
    int d  = threadIdx.x;
    float mg = -CUDART_INF_F;
#pragma unroll 4
    for (int i = 0; i < NSPLIT; i++) mg = fmaxf(mg, g_pm[g * NSPLIT + i]);
    float os = 0.f, ls = 0.f;
    for (int i = 0; i < NSPLIT; i++) {
        float wgt = __expf(g_pm[g * NSPLIT + i] - mg);
        ls = fmaf(wgt, g_pl[g * NSPLIT + i], ls);
        os = fmaf(wgt, g_pacc[(size_t)(g * NSPLIT + i) * DD + d], os);
    }
    int row = g_top[g];
    out[((size_t)bh * LQ + row) * DD + d] = os / ls;
}

// ---------------- cumsum(V): chunk sums (vectorized) -----------------------
__global__ __launch_bounds__(512) void k_csumA(const float* __restrict__ V)
{
    __shared__ __align__(16) float4 sred[32][16];   // 8 KB
    int c = blockIdx.x, bh = blockIdx.y;
    int t = threadIdx.x, r = t >> 4, c4 = t & 15;
    const float4* base = (const float4*)(V + ((size_t)bh * LQ + c * CHUNK) * DD);
    float4 a = __ldg(base + (size_t)r        * 16 + c4);
    float4 b = __ldg(base + (size_t)(r + 32) * 16 + c4);
    float4 d = __ldg(base + (size_t)(r + 64) * 16 + c4);
    float4 e = __ldg(base + (size_t)(r + 96) * 16 + c4);
    float4 s;
    s.x = (a.x + b.x) + (d.x + e.x);
    s.y = (a.y + b.y) + (d.y + e.y);
    s.z = (a.z + b.z) + (d.z + e.z);
    s.w = (a.w + b.w) + (d.w + e.w);
    sred[r][c4] = s;
    __syncthreads();
    if (t < 128) {
        int rr = t >> 4;
        float4 p0 = sred[rr][c4],      p1 = sred[rr + 8][c4];
        float4 p2 = sred[rr + 16][c4], p3 = sred[rr + 24][c4];
        float4 q;
        q.x = (p0.x + p1.x) + (p2.x + p3.x);
        q.y = (p0.y + p1.y) + (p2.y + p3.y);
        q.z = (p0.z + p1.z) + (p2.z + p3.z);
        q.w = (p0.w + p1.w) + (p2.w + p3.w);
        sred[rr][c4] = q;
    }
    __syncthreads();
    if (t < 16) {
        float4 q0 = sred[0][t], q1 = sred[1][t], q2 = sred[2][t], q3 = sred[3][t];
        float4 q4 = sred[4][t], q5 = sred[5][t], q6 = sred[6][t], q7 = sred[7][t];
        float4 q;
        q.x = ((q0.x + q1.x) + (q2.x + q3.x)) + ((q4.x + q5.x) + (q6.x + q7.x));
        q.y = ((q0.y + q1.y) + (q2.y + q3.y)) + ((q4.y + q5.y) + (q6.y + q7.y));
        q.z = ((q0.z + q1.z) + (q2.z + q3.z)) + ((q4.z + q5.z) + (q6.z + q7.z));
        q.w = ((q0.w + q1.w) + (q2.w + q3.w)) + ((q4.w + q5.w) + (q6.w + q7.w));
        ((float4*)(g_chunk + (bh * NCHUNK + c) * DD))[t] = q;
    }
}

// ---------------- cumsum(V): per-chunk scan, register-resident -------------
__global__ __launch_bounds__(512) void k_csumC(const float* __restrict__ V,
                                               float* __restrict__ out)
{
    __shared__ float gsum[8][64];
    int c = blockIdx.x, bh = blockIdx.y;
    int t = threadIdx.x, g = t >> 6, d = t & 63;

    float pre = 0.f;
    for (int j = 0; j < c; j++) pre += g_chunk[(bh * NCHUNK + j) * DD + d];

    const float* base = V + ((size_t)bh * LQ + c * CHUNK + g * 16) * DD + d;
    float v[16];
#pragma unroll
    for (int i = 0; i < 16; i++) v[i] = base[i * DD];
#pragma unroll
    for (int i = 1; i < 16; i++) v[i] += v[i - 1];
    gsum[g][d] = v[15];
    __syncthreads();
    float off = pre;
#pragma unroll
    for (int j = 0; j < 7; j++) if (j < g) off += gsum[j][d];
    float* ob = out + ((size_t)bh * LQ + c * CHUNK + g * 16) * DD + d;
#pragma unroll
    for (int i = 0; i < 16; i++) ob[i * DD] = v[i] + off;
}

// ---------------- launcher --------------------------------------------------
extern "C" void kernel_launch(void* const* d_in, const int* in_sizes, int n_in,
                              void* d_out, int out_size)
{
    (void)in_sizes; (void)n_in; (void)out_size;
    const float* Q   = (const float*)d_in[0];
    const float* K   = (const float*)d_in[1];
    const float* V   = (const float*)d_in[2];
    const int*   idx = (const int*)d_in[3];
    float* out = (float*)d_out;

    k_M<<<BH * LQ / 8, 256>>>(Q, K, idx);
    k_top<<<BH, 256>>>();
    k_attn<<<dim3(NSPLIT, BH), 256>>>(Q, K, V);
    k_csumA<<<dim3(NCHUNK, BH), 512>>>(V);
    k_csumC<<<dim3(NCHUNK, BH), 512>>>(V, out);
    k_comb<<<BH * UU, 64>>>(out);
}

// round 11
// speedup vs baseline: 2.1633x; 1.0436x over previous
#include <cuda_runtime.h>
#include <math_constants.h>

#define BH      16
#define LQ      4096
#define DD      64
#define SK      45
#define UU      45
#define NSPLIT  32
#define SPLIT_KEYS 128
#define NCHUNK  32
#define CHUNK   128

// ---------------- scratch (device globals; no allocation allowed) ----------
__device__ __align__(16) float g_M[BH * LQ];
__device__ __align__(16) int   g_top[BH * UU];
__device__ __align__(16) float g_pm[BH * UU * NSPLIT];
__device__ __align__(16) float g_pl[BH * UU * NSPLIT];
__device__ __align__(16) float g_pacc[BH * UU * NSPLIT * DD];
__device__ __align__(16) float g_chunk[BH * NCHUNK * DD];

// ---------------- L1: csumA (512 blocks) ⊕ k_M (8192 blocks) ---------------
// csumA blocks first: DRAM-bound chunk sums ride under k_M's LTS-bound waves.
__global__ __launch_bounds__(256) void k_L1(const float* __restrict__ Q,
                                            const float* __restrict__ K,
                                            const float* __restrict__ V,
                                            const int*   __restrict__ idx)
{
    __shared__ int sidx[8][48];
    __shared__ __align__(16) float4 sredA[16][16];   // 4 KB (csumA role)

    int t = threadIdx.x;

    if (blockIdx.x < 512) {
        // ---------------- csumA role: sum of V rows per 128-chunk ----------
        int i = blockIdx.x;
        int c = i & 31, bh = i >> 5;
        int r = t >> 4, c4 = t & 15;
        const float4* base = (const float4*)(V + ((size_t)bh * LQ + c * CHUNK) * DD);
        float4 a = __ldg(base + (size_t)r * 16 + c4);
#pragma unroll
        for (int j = 1; j < 8; j++) {
            float4 b = __ldg(base + (size_t)(r + 16 * j) * 16 + c4);
            a.x += b.x; a.y += b.y; a.z += b.z; a.w += b.w;
        }
        sredA[r][c4] = a;
        __syncthreads();
        if (t < 64) {
            int rr = t >> 4, cc = t & 15;
            float4 p0 = sredA[rr][cc],     p1 = sredA[rr + 4][cc];
            float4 p2 = sredA[rr + 8][cc], p3 = sredA[rr + 12][cc];
            float4 q;
            q.x = (p0.x + p1.x) + (p2.x + p3.x);
            q.y = (p0.y + p1.y) + (p2.y + p3.y);
            q.z = (p0.z + p1.z) + (p2.z + p3.z);
            q.w = (p0.w + p1.w) + (p2.w + p3.w);
            sredA[rr][cc] = q;
        }
        __syncthreads();
        if (t < 16) {
            float4 q0 = sredA[0][t], q1 = sredA[1][t], q2 = sredA[2][t], q3 = sredA[3][t];
            float4 q;
            q.x = (q0.x + q1.x) + (q2.x + q3.x);
            q.y = (q0.y + q1.y) + (q2.y + q3.y);
            q.z = (q0.z + q1.z) + (q2.z + q3.z);
            q.w = (q0.w + q1.w) + (q2.w + q3.w);
            ((float4*)(g_chunk + (bh * NCHUNK + c) * DD))[t] = q;
        }
        return;
    }

    // ---------------- k_M role (round-8 pipelined gather) ------------------
    int w = t >> 5, lane = t & 31;
    int gw = (blockIdx.x - 512) * 8 + w;
    int bh = gw >> 12, q = gw & (LQ - 1);
    const float4* Kb4 = (const float4*)(K + (size_t)bh * (LQ * DD));

    sidx[w][lane] = idx[q * SK + lane];
    if (lane < SK - 32) sidx[w][32 + lane] = idx[q * SK + 32 + lane];
    if (lane >= 29)     sidx[w][16 + lane] = idx[q * SK + SK - 1];  // pad 45..47
    __syncwarp();

    int r = lane >> 3, c = lane & 7;
    const float4* Qr4 = (const float4*)(Q + ((size_t)bh * LQ + q) * DD);
    float4 qa = Qr4[c];
    float4 qb = Qr4[c + 8];

    float4 A0[4], B0[4], A1[4], B1[4];
    float mx = -CUDART_INF_F, sm = 0.f;

#pragma unroll
    for (int i = 0; i < 4; i++) {
        const float4* kp = Kb4 + (size_t)sidx[w][4 * i + r] * 16;
        A0[i] = __ldg(kp + c); B0[i] = __ldg(kp + c + 8);
    }
#pragma unroll
    for (int i = 0; i < 4; i++) {
        const float4* kp = Kb4 + (size_t)sidx[w][16 + 4 * i + r] * 16;
        A1[i] = __ldg(kp + c); B1[i] = __ldg(kp + c + 8);
    }

#pragma unroll
    for (int blk = 0; blk < 3; blk++) {
#pragma unroll
        for (int i = 0; i < 4; i++) {
            float4 ka = A0[i], kb = B0[i];
            float d;
            d = ka.x * qa.x;
            d = fmaf(ka.y, qa.y, d);
            d = fmaf(ka.z, qa.z, d);
            d = fmaf(ka.w, qa.w, d);
            d = fmaf(kb.x, qb.x, d);
            d = fmaf(kb.y, qb.y, d);
            d = fmaf(kb.z, qb.z, d);
            d = fmaf(kb.w, qb.w, d);
            d += __shfl_xor_sync(0xffffffffu, d, 1);
            d += __shfl_xor_sync(0xffffffffu, d, 2);
            d += __shfl_xor_sync(0xffffffffu, d, 4);
            int samp = 16 * blk + 4 * i + r;
            if (samp < SK) { mx = fmaxf(mx, d); sm += d; }
        }
#pragma unroll
        for (int i = 0; i < 4; i++) { A0[i] = A1[i]; B0[i] = B1[i]; }
        if (blk == 0) {
#pragma unroll
            for (int i = 0; i < 4; i++) {
                const float4* kp = Kb4 + (size_t)sidx[w][32 + 4 * i + r] * 16;
                A1[i] = __ldg(kp + c); B1[i] = __ldg(kp + c + 8);
            }
        }
    }

    mx = fmaxf(mx, __shfl_xor_sync(0xffffffffu, mx, 8));
    sm +=          __shfl_xor_sync(0xffffffffu, sm, 8);
    mx = fmaxf(mx, __shfl_xor_sync(0xffffffffu, mx, 16));
    sm +=          __shfl_xor_sync(0xffffffffu, sm, 16);
    if (lane == 0) g_M[gw] = mx - sm * (1.0f / (float)LQ);
}

// ---------------- L2: k_top (16 blocks) ⊕ csumC (512 blocks) ---------------
__global__ __launch_bounds__(256) void k_L2(const float* __restrict__ V,
                                            float* __restrict__ out)
{
    __shared__ unsigned long long ckeys[16 * UU];    // top role
    __shared__ int stop[UU];
    __shared__ float gsumC[4][64];                   // csumC role

    int t = threadIdx.x;

    if (blockIdx.x >= 16) {
        // ---------------- csumC role: per-chunk scan (256 threads) ---------
        int i = blockIdx.x - 16;
        int c = i & 31, bh = i >> 5;
        int g = t >> 6, d = t & 63;

        float pre = 0.f;
        for (int j = 0; j < c; j++) pre += g_chunk[(bh * NCHUNK + j) * DD + d];

        const float* base = V + ((size_t)bh * LQ + c * CHUNK + g * 32) * DD + d;
        float v[32];
#pragma unroll
        for (int k = 0; k < 32; k++) v[k] = base[k * DD];
#pragma unroll
        for (int k = 1; k < 32; k++) v[k] += v[k - 1];
        gsumC[g][d] = v[31];
        __syncthreads();
        float off = pre;
#pragma unroll
        for (int j = 0; j < 3; j++) if (j < g) off += gsumC[j][d];
        float* ob = out + ((size_t)bh * LQ + c * CHUNK + g * 32) * DD + d;
#pragma unroll
        for (int k = 0; k < 32; k++) ob[k * DD] = v[k] + off;
        return;
    }

    // ---------------- k_top role: top-45, index-sorted ---------------------
    int bh = blockIdx.x, w = t >> 5, lane = t & 31;
    int h = lane >> 4, sl = lane & 15;
    int list = 2 * w + h;
    int base = w * 512 + h * 256 + sl;

    unsigned long long k[16];
#pragma unroll
    for (int kk = 0; kk < 16; kk++) {
        int i = base + 16 * kk;
        unsigned int u = __float_as_uint(g_M[bh * LQ + i]);
        u ^= (unsigned int)(((int)u >> 31)) | 0x80000000u;
        k[kk] = ((unsigned long long)u << 32) | (unsigned long long)(0xFFFFFFFFu - (unsigned int)i);
    }

    for (int it = 0; it < UU; it++) {
        unsigned long long b = k[0];
#pragma unroll
        for (int kk = 1; kk < 16; kk++) b = (k[kk] > b) ? k[kk] : b;
#pragma unroll
        for (int off = 8; off > 0; off >>= 1) {
            unsigned long long o = __shfl_xor_sync(0xffffffffu, b, off);
            b = (o > b) ? o : b;
        }
        if (sl == 0) ckeys[list * UU + it] = b;
#pragma unroll
        for (int kk = 0; kk < 16; kk++) if (k[kk] == b) k[kk] = 0ull;
    }
    __syncthreads();

    for (int x = t; x < 16 * UU; x += 256) {
        unsigned long long Kx = ckeys[x];
        int rank = 0;
#pragma unroll
        for (int L = 0; L < 16; L++) {
            const unsigned long long* a = &ckeys[L * UU];
            int lo = 0, hi = UU;
            while (lo < hi) {
                int mid = (lo + hi) >> 1;
                if (a[mid] > Kx) lo = mid + 1; else hi = mid;
            }
            rank += lo;
        }
        if (rank < UU)
            stop[rank] = (int)(0xFFFFFFFFu - (unsigned int)(Kx & 0xFFFFFFFFull));
    }
    __syncthreads();

    if (t < UU) {
        int my = stop[t], cnt = 0;
#pragma unroll 9
        for (int j = 0; j < UU; j++) cnt += (stop[j] < my);
        g_top[bh * UU + cnt] = my;
    }
}

// ---------------- Stage 3: split-KV flash attention (round-10) -------------
#define KT(d, kk) KP[(d) * 66 + (kk)]
#define PW(u, kk) KP[(u) * 68 + (kk)]

__global__ __launch_bounds__(256) void k_attn(const float* __restrict__ Q,
                                              const float* __restrict__ K,
                                              const float* __restrict__ V)
{
    __shared__ __align__(16) float Qs[48][DD];
    __shared__ __align__(16) float KP[DD * 66];
    __shared__ __align__(16) float Vs[64][DD];
    __shared__ int tops[UU];

    int split = blockIdx.x, bh = blockIdx.y;
    int t = threadIdx.x, w = t >> 5, lane = t & 31;
    int band = (w < 4) ? w : 11 - w;

    if (t < UU) tops[t] = g_top[bh * UU + t];
    __syncthreads();
    const float scale = 0.125f;
    for (int r = w; r < UU; r += 8) {
        float2 v = *(const float2*)(Q + ((size_t)bh * LQ + tops[r]) * DD + 2 * lane);
        Qs[r][2 * lane]     = v.x * scale;
        Qs[r][2 * lane + 1] = v.y * scale;
    }
    float mx[6], l[6]; float2 acc[6];
#pragma unroll
    for (int j = 0; j < 6; j++) { mx[j] = -CUDART_INF_F; l[j] = 0.f; acc[j] = make_float2(0.f, 0.f); }
    __syncthreads();
    int s_maxtop = tops[UU - 1];

    int k0 = split * SPLIT_KEYS;
    for (int sub = 0; sub < SPLIT_KEYS / 64; sub++) {
        int kb = k0 + sub * 64;
        __syncthreads();
        if (kb > s_maxtop) break;

        {
            const float4* Kc = (const float4*)(K + ((size_t)bh * LQ + kb) * DD);
            const float4* Vc = (const float4*)(V + ((size_t)bh * LQ + kb) * DD);
#pragma unroll
            for (int rep = 0; rep < 4; rep++) {
                int idx4 = t + 256 * rep;
                int kk = idx4 >> 4, c4 = idx4 & 15;
                float4 kv = __ldg(Kc + idx4);
                KT(4 * c4 + 0, kk) = kv.x;
                KT(4 * c4 + 1, kk) = kv.y;
                KT(4 * c4 + 2, kk) = kv.z;
                KT(4 * c4 + 3, kk) = kv.w;
                *(float4*)&Vs[kk][4 * c4] = __ldg(Vc + idx4);
            }
        }
        __syncthreads();

        bool act[6]; bool any = false;
#pragma unroll
        for (int j = 0; j < 6; j++) {
            int u = 6 * band + j;
            act[j] = (u < UU) && (kb <= tops[u]);
            any |= act[j];
        }

        float e0[6], e1[6];
        if (any) {
            float s0[6], s1[6];
#pragma unroll
            for (int j = 0; j < 6; j++) { s0[j] = 0.f; s1[j] = 0.f; }
#pragma unroll
            for (int d4 = 0; d4 < DD; d4 += 4) {
                float2 kt0 = *(const float2*)&KT(d4 + 0, 2 * lane);
                float2 kt1 = *(const float2*)&KT(d4 + 1, 2 * lane);
                float2 kt2 = *(const float2*)&KT(d4 + 2, 2 * lane);
                float2 kt3 = *(const float2*)&KT(d4 + 3, 2 * lane);
#pragma unroll
                for (int j = 0; j < 6; j++) {
                    if (act[j]) {
                        float4 qv = *(const float4*)&Qs[6 * band + j][d4];
                        s0[j] = fmaf(qv.x, kt0.x, s0[j]);
                        s0[j] = fmaf(qv.y, kt1.x, s0[j]);
                        s0[j] = fmaf(qv.z, kt2.x, s0[j]);
                        s0[j] = fmaf(qv.w, kt3.x, s0[j]);
                        s1[j] = fmaf(qv.x, kt0.y, s1[j]);
                        s1[j] = fmaf(qv.y, kt1.y, s1[j]);
                        s1[j] = fmaf(qv.z, kt2.y, s1[j]);
                        s1[j] = fmaf(qv.w, kt3.y, s1[j]);
                    }
                }
            }

            int kk0 = kb + 2 * lane;
#pragma unroll
            for (int j = 0; j < 6; j++) {
                e0[j] = 0.f; e1[j] = 0.f;
                if (!act[j]) continue;
                int mu = tops[6 * band + j];
                float a = (kk0     <= mu) ? s0[j] : -CUDART_INF_F;
                float b = (kk0 + 1 <= mu) ? s1[j] : -CUDART_INF_F;
                float lm = fmaxf(a, b);
#pragma unroll
                for (int o = 16; o > 0; o >>= 1) lm = fmaxf(lm, __shfl_xor_sync(0xffffffffu, lm, o));
                float nm   = fmaxf(mx[j], lm);
                float corr = __expf(mx[j] - nm);
                float ea = __expf(a - nm);
                float eb = __expf(b - nm);
                float ts = ea + eb;
#pragma unroll
                for (int o = 16; o > 0; o >>= 1) ts += __shfl_xor_sync(0xffffffffu, ts, o);
                mx[j] = nm;
                l[j]  = l[j] * corr + ts;
                acc[j].x *= corr; acc[j].y *= corr;
                e0[j] = ea; e1[j] = eb;
            }
        }

        __syncthreads();
        if (any) {
#pragma unroll
            for (int j = 0; j < 6; j++) {
                if (act[j]) {
                    *(float2*)&PW(6 * band + j, 2 * lane) = make_float2(e0[j], e1[j]);
                }
            }
        }
        __syncthreads();

        if (any) {
#pragma unroll
            for (int kk4 = 0; kk4 < 64; kk4 += 4) {
                float2 vv0 = *(const float2*)&Vs[kk4 + 0][2 * lane];
                float2 vv1 = *(const float2*)&Vs[kk4 + 1][2 * lane];
                float2 vv2 = *(const float2*)&Vs[kk4 + 2][2 * lane];
                float2 vv3 = *(const float2*)&Vs[kk4 + 3][2 * lane];
#pragma unroll
                for (int j = 0; j < 6; j++) {
                    if (act[j]) {
                        float4 p = *(const float4*)&PW(6 * band + j, kk4);
                        acc[j].x = fmaf(p.x, vv0.x, acc[j].x);
                        acc[j].x = fmaf(p.y, vv1.x, acc[j].x);
                        acc[j].x = fmaf(p.z, vv2.x, acc[j].x);
                        acc[j].x = fmaf(p.w, vv3.x, acc[j].x);
                        acc[j].y = fmaf(p.x, vv0.y, acc[j].y);
                        acc[j].y = fmaf(p.y, vv1.y, acc[j].y);
                        acc[j].y = fmaf(p.z, vv2.y, acc[j].y);
                        acc[j].y = fmaf(p.w, vv3.y, acc[j].y);
                    }
                }
            }
        }
    }

#pragma unroll
    for (int j = 0; j < 6; j++) {
        int u = 6 * band + j;
        if (u >= UU) continue;
        int pb = (bh * UU + u) * NSPLIT + split;
        *(float2*)&g_pacc[(size_t)pb * DD + 2 * lane] = acc[j];
        if (lane == 0) { g_pm[pb] = mx[j]; g_pl[pb] = l[j]; }
    }
}

// ---------------- combine split partials into selected rows ----------------
__global__ __launch_bounds__(64) void k_comb(float* __restrict__ out)
{
    int g  = blockIdx.x;                    // bh*UU + u
    int bh = g / UU;
    int d  = threadIdx.x;
    float mg = -CUDART_INF_F;
#pragma unroll 4
    for (int i = 0; i < NSPLIT; i++) mg = fmaxf(mg, g_pm[g * NSPLIT + i]);
    float os = 0.f, ls = 0.f;
    for (int i = 0; i < NSPLIT; i++) {
        float wgt = __expf(g_pm[g * NSPLIT + i] - mg);
        ls = fmaf(wgt, g_pl[g * NSPLIT + i], ls);
        os = fmaf(wgt, g_pacc[(size_t)(g * NSPLIT + i) * DD + d], os);
    }
    int row = g_top[g];
    out[((size_t)bh * LQ + row) * DD + d] = os / ls;
}

// ---------------- launcher --------------------------------------------------
extern "C" void kernel_launch(void* const* d_in, const int* in_sizes, int n_in,
                              void* d_out, int out_size)
{
    (void)in_sizes; (void)n_in; (void)out_size;
    const float* Q   = (const float*)d_in[0];
    const float* K   = (const float*)d_in[1];
    const float* V   = (const float*)d_in[2];
    const int*   idx = (const int*)d_in[3];
    float* out = (float*)d_out;

    k_L1<<<512 + BH * LQ / 8, 256>>>(Q, K, V, idx);
    k_L2<<<16 + NCHUNK * BH, 256>>>(V, out);
    k_attn<<<dim3(NSPLIT, BH), 256>>>(Q, K, V);
    k_comb<<<BH * UU, 64>>>(out);
}

// round 12
// speedup vs baseline: 2.1932x; 1.0139x over previous
#include <cuda_runtime.h>
#include <math_constants.h>

#define BH      16
#define LQ      4096
#define DD      64
#define SK      45
#define UU      45
#define NSPLIT  32
#define SPLIT_KEYS 128
#define NCHUNK  32
#define CHUNK   128

// ---------------- scratch (device globals; no allocation allowed) ----------
__device__ __align__(16) float g_M[BH * LQ];
__device__ __align__(16) int   g_top[BH * UU];
__device__ __align__(16) float g_pm[BH * UU * NSPLIT];
__device__ __align__(16) float g_pl[BH * UU * NSPLIT];
__device__ __align__(16) float g_pacc[BH * UU * NSPLIT * DD];
__device__ __align__(16) float g_chunk[BH * NCHUNK * DD];

// ---------------- L1: csumA (512 blocks) ⊕ k_M (8192 blocks) ---------------
__global__ __launch_bounds__(256) void k_L1(const float* __restrict__ Q,
                                            const float* __restrict__ K,
                                            const float* __restrict__ V,
                                            const int*   __restrict__ idx)
{
    __shared__ int sidx[8][48];
    __shared__ __align__(16) float4 sredA[16][16];   // 4 KB (csumA role)

    int t = threadIdx.x;

    if (blockIdx.x < 512) {
        // ---------------- csumA role: sum of V rows per 128-chunk ----------
        int i = blockIdx.x;
        int c = i & 31, bh = i >> 5;
        int r = t >> 4, c4 = t & 15;
        const float4* base = (const float4*)(V + ((size_t)bh * LQ + c * CHUNK) * DD);
        float4 a = __ldg(base + (size_t)r * 16 + c4);
#pragma unroll
        for (int j = 1; j < 8; j++) {
            float4 b = __ldg(base + (size_t)(r + 16 * j) * 16 + c4);
            a.x += b.x; a.y += b.y; a.z += b.z; a.w += b.w;
        }
        sredA[r][c4] = a;
        __syncthreads();
        if (t < 64) {
            int rr = t >> 4, cc = t & 15;
            float4 p0 = sredA[rr][cc],     p1 = sredA[rr + 4][cc];
            float4 p2 = sredA[rr + 8][cc], p3 = sredA[rr + 12][cc];
            float4 q;
            q.x = (p0.x + p1.x) + (p2.x + p3.x);
            q.y = (p0.y + p1.y) + (p2.y + p3.y);
            q.z = (p0.z + p1.z) + (p2.z + p3.z);
            q.w = (p0.w + p1.w) + (p2.w + p3.w);
            sredA[rr][cc] = q;
        }
        __syncthreads();
        if (t < 16) {
            float4 q0 = sredA[0][t], q1 = sredA[1][t], q2 = sredA[2][t], q3 = sredA[3][t];
            float4 q;
            q.x = (q0.x + q1.x) + (q2.x + q3.x);
            q.y = (q0.y + q1.y) + (q2.y + q3.y);
            q.z = (q0.z + q1.z) + (q2.z + q3.z);
            q.w = (q0.w + q1.w) + (q2.w + q3.w);
            ((float4*)(g_chunk + (bh * NCHUNK + c) * DD))[t] = q;
        }
        return;
    }

    // ---------------- k_M role (round-8 pipelined gather) ------------------
    int w = t >> 5, lane = t & 31;
    int gw = (blockIdx.x - 512) * 8 + w;
    int bh = gw >> 12, q = gw & (LQ - 1);
    const float4* Kb4 = (const float4*)(K + (size_t)bh * (LQ * DD));

    sidx[w][lane] = idx[q * SK + lane];
    if (lane < SK - 32) sidx[w][32 + lane] = idx[q * SK + 32 + lane];
    if (lane >= 29)     sidx[w][16 + lane] = idx[q * SK + SK - 1];  // pad 45..47
    __syncwarp();

    int r = lane >> 3, c = lane & 7;
    const float4* Qr4 = (const float4*)(Q + ((size_t)bh * LQ + q) * DD);
    float4 qa = Qr4[c];
    float4 qb = Qr4[c + 8];

    float4 A0[4], B0[4], A1[4], B1[4];
    float mx = -CUDART_INF_F, sm = 0.f;

#pragma unroll
    for (int i = 0; i < 4; i++) {
        const float4* kp = Kb4 + (size_t)sidx[w][4 * i + r] * 16;
        A0[i] = __ldg(kp + c); B0[i] = __ldg(kp + c + 8);
    }
#pragma unroll
    for (int i = 0; i < 4; i++) {
        const float4* kp = Kb4 + (size_t)sidx[w][16 + 4 * i + r] * 16;
        A1[i] = __ldg(kp + c); B1[i] = __ldg(kp + c + 8);
    }

#pragma unroll
    for (int blk = 0; blk < 3; blk++) {
#pragma unroll
        for (int i = 0; i < 4; i++) {
            float4 ka = A0[i], kb = B0[i];
            float d;
            d = ka.x * qa.x;
            d = fmaf(ka.y, qa.y, d);
            d = fmaf(ka.z, qa.z, d);
            d = fmaf(ka.w, qa.w, d);
            d = fmaf(kb.x, qb.x, d);
            d = fmaf(kb.y, qb.y, d);
            d = fmaf(kb.z, qb.z, d);
            d = fmaf(kb.w, qb.w, d);
            d += __shfl_xor_sync(0xffffffffu, d, 1);
            d += __shfl_xor_sync(0xffffffffu, d, 2);
            d += __shfl_xor_sync(0xffffffffu, d, 4);
            int samp = 16 * blk + 4 * i + r;
            if (samp < SK) { mx = fmaxf(mx, d); sm += d; }
        }
#pragma unroll
        for (int i = 0; i < 4; i++) { A0[i] = A1[i]; B0[i] = B1[i]; }
        if (blk == 0) {
#pragma unroll
            for (int i = 0; i < 4; i++) {
                const float4* kp = Kb4 + (size_t)sidx[w][32 + 4 * i + r] * 16;
                A1[i] = __ldg(kp + c); B1[i] = __ldg(kp + c + 8);
            }
        }
    }

    mx = fmaxf(mx, __shfl_xor_sync(0xffffffffu, mx, 8));
    sm +=          __shfl_xor_sync(0xffffffffu, sm, 8);
    mx = fmaxf(mx, __shfl_xor_sync(0xffffffffu, mx, 16));
    sm +=          __shfl_xor_sync(0xffffffffu, sm, 16);
    if (lane == 0) g_M[gw] = mx - sm * (1.0f / (float)LQ);
}

// ---------------- L2: k_top (16 blocks) ⊕ csumC (512 blocks) ---------------
__global__ __launch_bounds__(256) void k_L2(const float* __restrict__ V,
                                            float* __restrict__ out)
{
    __shared__ unsigned long long ckeys[16 * UU];    // top role
    __shared__ int stop[UU];
    __shared__ float gsumC[4][64];                   // csumC role

    int t = threadIdx.x;

    if (blockIdx.x >= 16) {
        // ---------------- csumC role: per-chunk scan (256 threads) ---------
        int i = blockIdx.x - 16;
        int c = i & 31, bh = i >> 5;
        int g = t >> 6, d = t & 63;

        float pre = 0.f;
        for (int j = 0; j < c; j++) pre += g_chunk[(bh * NCHUNK + j) * DD + d];

        const float* base = V + ((size_t)bh * LQ + c * CHUNK + g * 32) * DD + d;
        float v[32];
#pragma unroll
        for (int k = 0; k < 32; k++) v[k] = base[k * DD];
#pragma unroll
        for (int k = 1; k < 32; k++) v[k] += v[k - 1];
        gsumC[g][d] = v[31];
        __syncthreads();
        float off = pre;
#pragma unroll
        for (int j = 0; j < 3; j++) if (j < g) off += gsumC[j][d];
        float* ob = out + ((size_t)bh * LQ + c * CHUNK + g * 32) * DD + d;
#pragma unroll
        for (int k = 0; k < 32; k++) ob[k * DD] = v[k] + off;
        return;
    }

    // ---------------- k_top role: top-45, index-sorted ---------------------
    int bh = blockIdx.x, w = t >> 5, lane = t & 31;
    int h = lane >> 4, sl = lane & 15;
    int list = 2 * w + h;
    int base = w * 512 + h * 256 + sl;

    unsigned long long k[16];
#pragma unroll
    for (int kk = 0; kk < 16; kk++) {
        int i = base + 16 * kk;
        unsigned int u = __float_as_uint(g_M[bh * LQ + i]);
        u ^= (unsigned int)(((int)u >> 31)) | 0x80000000u;
        k[kk] = ((unsigned long long)u << 32) | (unsigned long long)(0xFFFFFFFFu - (unsigned int)i);
    }

    for (int it = 0; it < UU; it++) {
        unsigned long long b = k[0];
#pragma unroll
        for (int kk = 1; kk < 16; kk++) b = (k[kk] > b) ? k[kk] : b;
#pragma unroll
        for (int off = 8; off > 0; off >>= 1) {
            unsigned long long o = __shfl_xor_sync(0xffffffffu, b, off);
            b = (o > b) ? o : b;
        }
        if (sl == 0) ckeys[list * UU + it] = b;
#pragma unroll
        for (int kk = 0; kk < 16; kk++) if (k[kk] == b) k[kk] = 0ull;
    }
    __syncthreads();

    for (int x = t; x < 16 * UU; x += 256) {
        unsigned long long Kx = ckeys[x];
        int rank = 0;
#pragma unroll
        for (int L = 0; L < 16; L++) {
            const unsigned long long* a = &ckeys[L * UU];
            int lo = 0, hi = UU;
            while (lo < hi) {
                int mid = (lo + hi) >> 1;
                if (a[mid] > Kx) lo = mid + 1; else hi = mid;
            }
            rank += lo;
        }
        if (rank < UU)
            stop[rank] = (int)(0xFFFFFFFFu - (unsigned int)(Kx & 0xFFFFFFFFull));
    }
    __syncthreads();

    if (t < UU) {
        int my = stop[t], cnt = 0;
#pragma unroll 9
        for (int j = 0; j < UU; j++) cnt += (stop[j] < my);
        g_top[bh * UU + cnt] = my;
    }
}

// ---------------- Stage 3: split-KV flash attention (round-10) -------------
#define KT(d, kk) KP[(d) * 66 + (kk)]
#define PW(u, kk) KP[(u) * 68 + (kk)]

__global__ __launch_bounds__(256) void k_attn(const float* __restrict__ Q,
                                              const float* __restrict__ K,
                                              const float* __restrict__ V)
{
    __shared__ __align__(16) float Qs[48][DD];
    __shared__ __align__(16) float KP[DD * 66];
    __shared__ __align__(16) float Vs[64][DD];
    __shared__ int tops[UU];

    int split = blockIdx.x, bh = blockIdx.y;
    int t = threadIdx.x, w = t >> 5, lane = t & 31;
    int band = (w < 4) ? w : 11 - w;

    if (t < UU) tops[t] = g_top[bh * UU + t];
    __syncthreads();
    const float scale = 0.125f;
    for (int r = w; r < UU; r += 8) {
        float2 v = *(const float2*)(Q + ((size_t)bh * LQ + tops[r]) * DD + 2 * lane);
        Qs[r][2 * lane]     = v.x * scale;
        Qs[r][2 * lane + 1] = v.y * scale;
    }
    float mx[6], l[6]; float2 acc[6];
#pragma unroll
    for (int j = 0; j < 6; j++) { mx[j] = -CUDART_INF_F; l[j] = 0.f; acc[j] = make_float2(0.f, 0.f); }
    __syncthreads();
    int s_maxtop = tops[UU - 1];

    int k0 = split * SPLIT_KEYS;
    for (int sub = 0; sub < SPLIT_KEYS / 64; sub++) {
        int kb = k0 + sub * 64;
        __syncthreads();
        if (kb > s_maxtop) break;

        {
            const float4* Kc = (const float4*)(K + ((size_t)bh * LQ + kb) * DD);
            const float4* Vc = (const float4*)(V + ((size_t)bh * LQ + kb) * DD);
#pragma unroll
            for (int rep = 0; rep < 4; rep++) {
                int idx4 = t + 256 * rep;
                int kk = idx4 >> 4, c4 = idx4 & 15;
                float4 kv = __ldg(Kc + idx4);
                KT(4 * c4 + 0, kk) = kv.x;
                KT(4 * c4 + 1, kk) = kv.y;
                KT(4 * c4 + 2, kk) = kv.z;
                KT(4 * c4 + 3, kk) = kv.w;
                *(float4*)&Vs[kk][4 * c4] = __ldg(Vc + idx4);
            }
        }
        __syncthreads();

        bool act[6]; bool any = false;
#pragma unroll
        for (int j = 0; j < 6; j++) {
            int u = 6 * band + j;
            act[j] = (u < UU) && (kb <= tops[u]);
            any |= act[j];
        }

        float e0[6], e1[6];
        if (any) {
            float s0[6], s1[6];
#pragma unroll
            for (int j = 0; j < 6; j++) { s0[j] = 0.f; s1[j] = 0.f; }
#pragma unroll
            for (int d4 = 0; d4 < DD; d4 += 4) {
                float2 kt0 = *(const float2*)&KT(d4 + 0, 2 * lane);
                float2 kt1 = *(const float2*)&KT(d4 + 1, 2 * lane);
                float2 kt2 = *(const float2*)&KT(d4 + 2, 2 * lane);
                float2 kt3 = *(const float2*)&KT(d4 + 3, 2 * lane);
#pragma unroll
                for (int j = 0; j < 6; j++) {
                    if (act[j]) {
                        float4 qv = *(const float4*)&Qs[6 * band + j][d4];
                        s0[j] = fmaf(qv.x, kt0.x, s0[j]);
                        s0[j] = fmaf(qv.y, kt1.x, s0[j]);
                        s0[j] = fmaf(qv.z, kt2.x, s0[j]);
                        s0[j] = fmaf(qv.w, kt3.x, s0[j]);
                        s1[j] = fmaf(qv.x, kt0.y, s1[j]);
                        s1[j] = fmaf(qv.y, kt1.y, s1[j]);
                        s1[j] = fmaf(qv.z, kt2.y, s1[j]);
                        s1[j] = fmaf(qv.w, kt3.y, s1[j]);
                    }
                }
            }

            int kk0 = kb + 2 * lane;
#pragma unroll
            for (int j = 0; j < 6; j++) {
                e0[j] = 0.f; e1[j] = 0.f;
                if (!act[j]) continue;
                int mu = tops[6 * band + j];
                float a = (kk0     <= mu) ? s0[j] : -CUDART_INF_F;
                float b = (kk0 + 1 <= mu) ? s1[j] : -CUDART_INF_F;
                float lm = fmaxf(a, b);
#pragma unroll
                for (int o = 16; o > 0; o >>= 1) lm = fmaxf(lm, __shfl_xor_sync(0xffffffffu, lm, o));
                float nm   = fmaxf(mx[j], lm);
                float corr = __expf(mx[j] - nm);
                float ea = __expf(a - nm);
                float eb = __expf(b - nm);
                float ts = ea + eb;
#pragma unroll
                for (int o = 16; o > 0; o >>= 1) ts += __shfl_xor_sync(0xffffffffu, ts, o);
                mx[j] = nm;
                l[j]  = l[j] * corr + ts;
                acc[j].x *= corr; acc[j].y *= corr;
                e0[j] = ea; e1[j] = eb;
            }
        }

        __syncthreads();
        if (any) {
#pragma unroll
            for (int j = 0; j < 6; j++) {
                if (act[j]) {
                    *(float2*)&PW(6 * band + j, 2 * lane) = make_float2(e0[j], e1[j]);
                }
            }
        }
        __syncthreads();

        if (any) {
#pragma unroll
            for (int kk4 = 0; kk4 < 64; kk4 += 4) {
                float2 vv0 = *(const float2*)&Vs[kk4 + 0][2 * lane];
                float2 vv1 = *(const float2*)&Vs[kk4 + 1][2 * lane];
                float2 vv2 = *(const float2*)&Vs[kk4 + 2][2 * lane];
                float2 vv3 = *(const float2*)&Vs[kk4 + 3][2 * lane];
#pragma unroll
                for (int j = 0; j < 6; j++) {
                    if (act[j]) {
                        float4 p = *(const float4*)&PW(6 * band + j, kk4);
                        acc[j].x = fmaf(p.x, vv0.x, acc[j].x);
                        acc[j].x = fmaf(p.y, vv1.x, acc[j].x);
                        acc[j].x = fmaf(p.z, vv2.x, acc[j].x);
                        acc[j].x = fmaf(p.w, vv3.x, acc[j].x);
                        acc[j].y = fmaf(p.x, vv0.y, acc[j].y);
                        acc[j].y = fmaf(p.y, vv1.y, acc[j].y);
                        acc[j].y = fmaf(p.z, vv2.y, acc[j].y);
                        acc[j].y = fmaf(p.w, vv3.y, acc[j].y);
                    }
                }
            }
        }
    }

#pragma unroll
    for (int j = 0; j < 6; j++) {
        int u = 6 * band + j;
        if (u >= UU) continue;
        int pb = (bh * UU + u) * NSPLIT + split;
        *(float2*)&g_pacc[(size_t)pb * DD + 2 * lane] = acc[j];
        if (lane == 0) { g_pm[pb] = mx[j]; g_pl[pb] = l[j]; }
    }
}

// ---------------- combine split partials (v2: 256 thr, 4-way split) --------
__global__ __launch_bounds__(256) void k_comb(float* __restrict__ out)
{
    __shared__ float sacc[4][64];
    __shared__ float sls[4];
    int g  = blockIdx.x;                    // bh*UU + u
    int bh = g / UU;
    int t  = threadIdx.x, grp = t >> 6, d = t & 63;

    // global max over 32 splits (broadcast loads, L1/L2-cached)
    const float* pmb = g_pm + g * NSPLIT;
    float mg = -CUDART_INF_F;
#pragma unroll
    for (int i = 0; i < NSPLIT; i++) mg = fmaxf(mg, __ldg(pmb + i));

    // group grp handles splits 8*grp .. 8*grp+7 (independent loads, MLP 8)
    const float* pab = g_pacc + (size_t)g * NSPLIT * DD;
    float os = 0.f, ls = 0.f;
#pragma unroll
    for (int i = 0; i < 8; i++) {
        int sp = 8 * grp + i;
        float wgt = __expf(__ldg(pmb + sp) - mg);
        os = fmaf(wgt, __ldg(pab + (size_t)sp * DD + d), os);
        ls = fmaf(wgt, __ldg(g_pl + g * NSPLIT + sp), ls);
    }
    sacc[grp][d] = os;
    if (d == 0) sls[grp] = ls;
    __syncthreads();

    if (t < 64) {
        float num = (sacc[0][t] + sacc[1][t]) + (sacc[2][t] + sacc[3][t]);
        float den = (sls[0] + sls[1]) + (sls[2] + sls[3]);
        int row = g_top[g];
        out[((size_t)bh * LQ + row) * DD + t] = num / den;
    }
}

// ---------------- launcher --------------------------------------------------
extern "C" void kernel_launch(void* const* d_in, const int* in_sizes, int n_in,
                              void* d_out, int out_size)
{
    (void)in_sizes; (void)n_in; (void)out_size;
    const float* Q   = (const float*)d_in[0];
    const float* K   = (const float*)d_in[1];
    const float* V   = (const float*)d_in[2];
    const int*   idx = (const int*)d_in[3];
    float* out = (float*)d_out;

    k_L1<<<512 + BH * LQ / 8, 256>>>(Q, K, V, idx);
    k_L2<<<16 + NCHUNK * BH, 256>>>(V, out);
    k_attn<<<dim3(NSPLIT, BH), 256>>>(Q, K, V);
    k_comb<<<BH * UU, 256>>>(out);
}

// round 15
// speedup vs baseline: 2.1943x; 1.0005x over previous
#include <cuda_runtime.h>
#include <math_constants.h>

#define BH      16
#define LQ      4096
#define DD      64
#define SK      45
#define UU      45
#define NSPLIT  32
#define SPLIT_KEYS 128
#define NCHUNK  32
#define CHUNK   128

// ---------------- scratch (device globals; no allocation allowed) ----------
__device__ __align__(16) float g_M[BH * LQ];
__device__ __align__(16) int   g_top[BH * UU];
__device__ __align__(16) float g_pm[BH * UU * NSPLIT];
__device__ __align__(16) float g_pl[BH * UU * NSPLIT];
__device__ __align__(16) float g_pacc[BH * UU * NSPLIT * DD];
__device__ __align__(16) float g_chunk[BH * NCHUNK * DD];

// ---------------- L1: csumA (512 blocks) ⊕ k_M (8192 blocks) ---------------
__global__ __launch_bounds__(256) void k_L1(const float* __restrict__ Q,
                                            const float* __restrict__ K,
                                            const float* __restrict__ V,
                                            const int*   __restrict__ idx)
{
    __shared__ int sidx[8][48];
    __shared__ __align__(16) float4 sredA[16][16];   // 4 KB (csumA role)

    int t = threadIdx.x;

    if (blockIdx.x < 512) {
        // ---------------- csumA role: sum of V rows per 128-chunk ----------
        int i = blockIdx.x;
        int c = i & 31, bh = i >> 5;
        int r = t >> 4, c4 = t & 15;
        const float4* base = (const float4*)(V + ((size_t)bh * LQ + c * CHUNK) * DD);
        float4 a = __ldg(base + (size_t)r * 16 + c4);
#pragma unroll
        for (int j = 1; j < 8; j++) {
            float4 b = __ldg(base + (size_t)(r + 16 * j) * 16 + c4);
            a.x += b.x; a.y += b.y; a.z += b.z; a.w += b.w;
        }
        sredA[r][c4] = a;
        __syncthreads();
        if (t < 64) {
            int rr = t >> 4, cc = t & 15;
            float4 p0 = sredA[rr][cc],     p1 = sredA[rr + 4][cc];
            float4 p2 = sredA[rr + 8][cc], p3 = sredA[rr + 12][cc];
            float4 q;
            q.x = (p0.x + p1.x) + (p2.x + p3.x);
            q.y = (p0.y + p1.y) + (p2.y + p3.y);
            q.z = (p0.z + p1.z) + (p2.z + p3.z);
            q.w = (p0.w + p1.w) + (p2.w + p3.w);
            sredA[rr][cc] = q;
        }
        __syncthreads();
        if (t < 16) {
            float4 q0 = sredA[0][t], q1 = sredA[1][t], q2 = sredA[2][t], q3 = sredA[3][t];
            float4 q;
            q.x = (q0.x + q1.x) + (q2.x + q3.x);
            q.y = (q0.y + q1.y) + (q2.y + q3.y);
            q.z = (q0.z + q1.z) + (q2.z + q3.z);
            q.w = (q0.w + q1.w) + (q2.w + q3.w);
            ((float4*)(g_chunk + (bh * NCHUNK + c) * DD))[t] = q;
        }
        return;
    }

    // ---------------- k_M role (round-8 pipelined gather) ------------------
    int w = t >> 5, lane = t & 31;
    int gw = (blockIdx.x - 512) * 8 + w;
    int bh = gw >> 12, q = gw & (LQ - 1);
    const float4* Kb4 = (const float4*)(K + (size_t)bh * (LQ * DD));

    sidx[w][lane] = idx[q * SK + lane];
    if (lane < SK - 32) sidx[w][32 + lane] = idx[q * SK + 32 + lane];
    if (lane >= 29)     sidx[w][16 + lane] = idx[q * SK + SK - 1];  // pad 45..47
    __syncwarp();

    int r = lane >> 3, c = lane & 7;
    const float4* Qr4 = (const float4*)(Q + ((size_t)bh * LQ + q) * DD);
    float4 qa = Qr4[c];
    float4 qb = Qr4[c + 8];

    float4 A0[4], B0[4], A1[4], B1[4];
    float mx = -CUDART_INF_F, sm = 0.f;

#pragma unroll
    for (int i = 0; i < 4; i++) {
        const float4* kp = Kb4 + (size_t)sidx[w][4 * i + r] * 16;
        A0[i] = __ldg(kp + c); B0[i] = __ldg(kp + c + 8);
    }
#pragma unroll
    for (int i = 0; i < 4; i++) {
        const float4* kp = Kb4 + (size_t)sidx[w][16 + 4 * i + r] * 16;
        A1[i] = __ldg(kp + c); B1[i] = __ldg(kp + c + 8);
    }

#pragma unroll
    for (int blk = 0; blk < 3; blk++) {
#pragma unroll
        for (int i = 0; i < 4; i++) {
            float4 ka = A0[i], kb = B0[i];
            float d;
            d = ka.x * qa.x;
            d = fmaf(ka.y, qa.y, d);
            d = fmaf(ka.z, qa.z, d);
            d = fmaf(ka.w, qa.w, d);
            d = fmaf(kb.x, qb.x, d);
            d = fmaf(kb.y, qb.y, d);
            d = fmaf(kb.z, qb.z, d);
            d = fmaf(kb.w, qb.w, d);
            d += __shfl_xor_sync(0xffffffffu, d, 1);
            d += __shfl_xor_sync(0xffffffffu, d, 2);
            d += __shfl_xor_sync(0xffffffffu, d, 4);
            int samp = 16 * blk + 4 * i + r;
            if (samp < SK) { mx = fmaxf(mx, d); sm += d; }
        }
#pragma unroll
        for (int i = 0; i < 4; i++) { A0[i] = A1[i]; B0[i] = B1[i]; }
        if (blk == 0) {
#pragma unroll
            for (int i = 0; i < 4; i++) {
                const float4* kp = Kb4 + (size_t)sidx[w][32 + 4 * i + r] * 16;
                A1[i] = __ldg(kp + c); B1[i] = __ldg(kp + c + 8);
            }
        }
    }

    mx = fmaxf(mx, __shfl_xor_sync(0xffffffffu, mx, 8));
    sm +=          __shfl_xor_sync(0xffffffffu, sm, 8);
    mx = fmaxf(mx, __shfl_xor_sync(0xffffffffu, mx, 16));
    sm +=          __shfl_xor_sync(0xffffffffu, sm, 16);
    if (lane == 0) g_M[gw] = mx - sm * (1.0f / (float)LQ);
}

// ---------------- L2: k_top (16 blocks) ------------------------------------
__global__ __launch_bounds__(256) void k_top()
{
    __shared__ unsigned long long ckeys[16 * UU];
    __shared__ int stop[UU];
    int bh = blockIdx.x, t = threadIdx.x, w = t >> 5, lane = t & 31;
    int h = lane >> 4, sl = lane & 15;
    int list = 2 * w + h;
    int base = w * 512 + h * 256 + sl;

    unsigned long long k[16];
#pragma unroll
    for (int kk = 0; kk < 16; kk++) {
        int i = base + 16 * kk;
        unsigned int u = __float_as_uint(g_M[bh * LQ + i]);
        u ^= (unsigned int)(((int)u >> 31)) | 0x80000000u;
        k[kk] = ((unsigned long long)u << 32) | (unsigned long long)(0xFFFFFFFFu - (unsigned int)i);
    }

    for (int it = 0; it < UU; it++) {
        unsigned long long b = k[0];
#pragma unroll
        for (int kk = 1; kk < 16; kk++) b = (k[kk] > b) ? k[kk] : b;
#pragma unroll
        for (int off = 8; off > 0; off >>= 1) {
            unsigned long long o = __shfl_xor_sync(0xffffffffu, b, off);
            b = (o > b) ? o : b;
        }
        if (sl == 0) ckeys[list * UU + it] = b;
#pragma unroll
        for (int kk = 0; kk < 16; kk++) if (k[kk] == b) k[kk] = 0ull;
    }
    __syncthreads();

    for (int x = t; x < 16 * UU; x += 256) {
        unsigned long long Kx = ckeys[x];
        int rank = 0;
#pragma unroll
        for (int L = 0; L < 16; L++) {
            const unsigned long long* a = &ckeys[L * UU];
            int lo = 0, hi = UU;
            while (lo < hi) {
                int mid = (lo + hi) >> 1;
                if (a[mid] > Kx) lo = mid + 1; else hi = mid;
            }
            rank += lo;
        }
        if (rank < UU)
            stop[rank] = (int)(0xFFFFFFFFu - (unsigned int)(Kx & 0xFFFFFFFFull));
    }
    __syncthreads();

    if (t < UU) {
        int my = stop[t], cnt = 0;
#pragma unroll 9
        for (int j = 0; j < UU; j++) cnt += (stop[j] < my);
        g_top[bh * UU + cnt] = my;
    }
}

// ---------------- L3: attn (512 blocks) ⊕ csumC (512 blocks) ---------------
#define KT(d, kk) KP[(d) * 66 + (kk)]
#define PW(u, kk) KP[(u) * 68 + (kk)]

__global__ __launch_bounds__(256) void k_L3(const float* __restrict__ Q,
                                            const float* __restrict__ K,
                                            const float* __restrict__ V,
                                            float* __restrict__ out)
{
    __shared__ __align__(16) float Qs[48][DD];
    __shared__ __align__(16) float KP[DD * 66];
    __shared__ __align__(16) float Vs[64][DD];
    __shared__ int tops[UU];
    __shared__ float gsumC[4][64];

    int t = threadIdx.x;

    if (blockIdx.x >= 512) {
        // ---------------- csumC role: per-chunk scan (256 threads) ---------
        int i = blockIdx.x - 512;
        int c = i & 31, bh = i >> 5;
        int g = t >> 6, d = t & 63;

        float pre = 0.f;
        for (int j = 0; j < c; j++) pre += g_chunk[(bh * NCHUNK + j) * DD + d];

        const float* base = V + ((size_t)bh * LQ + c * CHUNK + g * 32) * DD + d;
        float v[32];
#pragma unroll
        for (int k = 0; k < 32; k++) v[k] = base[k * DD];
#pragma unroll
        for (int k = 1; k < 32; k++) v[k] += v[k - 1];
        gsumC[g][d] = v[31];
        __syncthreads();
        float off = pre;
#pragma unroll
        for (int j = 0; j < 3; j++) if (j < g) off += gsumC[j][d];
        float* ob = out + ((size_t)bh * LQ + c * CHUNK + g * 32) * DD + d;
#pragma unroll
        for (int k = 0; k < 32; k++) ob[k * DD] = v[k] + off;
        return;
    }

    // ---------------- attn role (round-10, banded split-KV) ----------------
    int split = blockIdx.x & 31, bh = blockIdx.x >> 5;
    int w = t >> 5, lane = t & 31;
    int band = (w < 4) ? w : 11 - w;

    if (t < UU) tops[t] = g_top[bh * UU + t];
    __syncthreads();
    const float scale = 0.125f;
    for (int r = w; r < UU; r += 8) {
        float2 v = *(const float2*)(Q + ((size_t)bh * LQ + tops[r]) * DD + 2 * lane);
        Qs[r][2 * lane]     = v.x * scale;
        Qs[r][2 * lane + 1] = v.y * scale;
    }
    float mx[6], l[6]; float2 acc[6];
#pragma unroll
    for (int j = 0; j < 6; j++) { mx[j] = -CUDART_INF_F; l[j] = 0.f; acc[j] = make_float2(0.f, 0.f); }
    __syncthreads();
    int s_maxtop = tops[UU - 1];

    int k0 = split * SPLIT_KEYS;
    for (int sub = 0; sub < SPLIT_KEYS / 64; sub++) {
        int kb = k0 + sub * 64;
        __syncthreads();
        if (kb > s_maxtop) break;

        {
            const float4* Kc = (const float4*)(K + ((size_t)bh * LQ + kb) * DD);
            const float4* Vc = (const float4*)(V + ((size_t)bh * LQ + kb) * DD);
#pragma unroll
            for (int rep = 0; rep < 4; rep++) {
                int idx4 = t + 256 * rep;
                int kk = idx4 >> 4, c4 = idx4 & 15;
                float4 kv = __ldg(Kc + idx4);
                KT(4 * c4 + 0, kk) = kv.x;
                KT(4 * c4 + 1, kk) = kv.y;
                KT(4 * c4 + 2, kk) = kv.z;
                KT(4 * c4 + 3, kk) = kv.w;
                *(float4*)&Vs[kk][4 * c4] = __ldg(Vc + idx4);
            }
        }
        __syncthreads();

        bool act[6]; bool any = false;
#pragma unroll
        for (int j = 0; j < 6; j++) {
            int u = 6 * band + j;
            act[j] = (u < UU) && (kb <= tops[u]);
            any |= act[j];
        }

        float e0[6], e1[6];
        if (any) {
            float s0[6], s1[6];
#pragma unroll
            for (int j = 0; j < 6; j++) { s0[j] = 0.f; s1[j] = 0.f; }
#pragma unroll
            for (int d4 = 0; d4 < DD; d4 += 4) {
                float2 kt0 = *(const float2*)&KT(d4 + 0, 2 * lane);
                float2 kt1 = *(const float2*)&KT(d4 + 1, 2 * lane);
                float2 kt2 = *(const float2*)&KT(d4 + 2, 2 * lane);
                float2 kt3 = *(const float2*)&KT(d4 + 3, 2 * lane);
#pragma unroll
                for (int j = 0; j < 6; j++) {
                    if (act[j]) {
                        float4 qv = *(const float4*)&Qs[6 * band + j][d4];
                        s0[j] = fmaf(qv.x, kt0.x, s0[j]);
                        s0[j] = fmaf(qv.y, kt1.x, s0[j]);
                        s0[j] = fmaf(qv.z, kt2.x, s0[j]);
                        s0[j] = fmaf(qv.w, kt3.x, s0[j]);
                        s1[j] = fmaf(qv.x, kt0.y, s1[j]);
                        s1[j] = fmaf(qv.y, kt1.y, s1[j]);
                        s1[j] = fmaf(qv.z, kt2.y, s1[j]);
                        s1[j] = fmaf(qv.w, kt3.y, s1[j]);
                    }
                }
            }

            int kk0 = kb + 2 * lane;
#pragma unroll
            for (int j = 0; j < 6; j++) {
                e0[j] = 0.f; e1[j] = 0.f;
                if (!act[j]) continue;
                int mu = tops[6 * band + j];
                float a = (kk0     <= mu) ? s0[j] : -CUDART_INF_F;
                float b = (kk0 + 1 <= mu) ? s1[j] : -CUDART_INF_F;
                float lm = fmaxf(a, b);
#pragma unroll
                for (int o = 16; o > 0; o >>= 1) lm = fmaxf(lm, __shfl_xor_sync(0xffffffffu, lm, o));
                float nm   = fmaxf(mx[j], lm);
                float corr = __expf(mx[j] - nm);
                float ea = __expf(a - nm);
                float eb = __expf(b - nm);
                float ts = ea + eb;
#pragma unroll
                for (int o = 16; o > 0; o >>= 1) ts += __shfl_xor_sync(0xffffffffu, ts, o);
                mx[j] = nm;
                l[j]  = l[j] * corr + ts;
                acc[j].x *= corr; acc[j].y *= corr;
                e0[j] = ea; e1[j] = eb;
            }
        }

        __syncthreads();
        if (any) {
#pragma unroll
            for (int j = 0; j < 6; j++) {
                if (act[j]) {
                    *(float2*)&PW(6 * band + j, 2 * lane) = make_float2(e0[j], e1[j]);
                }
            }
        }
        __syncthreads();

        if (any) {
#pragma unroll
            for (int kk4 = 0; kk4 < 64; kk4 += 4) {
                float2 vv0 = *(const float2*)&Vs[kk4 + 0][2 * lane];
                float2 vv1 = *(const float2*)&Vs[kk4 + 1][2 * lane];
                float2 vv2 = *(const float2*)&Vs[kk4 + 2][2 * lane];
                float2 vv3 = *(const float2*)&Vs[kk4 + 3][2 * lane];
#pragma unroll
                for (int j = 0; j < 6; j++) {
                    if (act[j]) {
                        float4 p = *(const float4*)&PW(6 * band + j, kk4);
                        acc[j].x = fmaf(p.x, vv0.x, acc[j].x);
                        acc[j].x = fmaf(p.y, vv1.x, acc[j].x);
                        acc[j].x = fmaf(p.z, vv2.x, acc[j].x);
                        acc[j].x = fmaf(p.w, vv3.x, acc[j].x);
                        acc[j].y = fmaf(p.x, vv0.y, acc[j].y);
                        acc[j].y = fmaf(p.y, vv1.y, acc[j].y);
                        acc[j].y = fmaf(p.z, vv2.y, acc[j].y);
                        acc[j].y = fmaf(p.w, vv3.y, acc[j].y);
                    }
                }
            }
        }
    }

#pragma unroll
    for (int j = 0; j < 6; j++) {
        int u = 6 * band + j;
        if (u >= UU) continue;
        int pb = (bh * UU + u) * NSPLIT + split;
        *(float2*)&g_pacc[(size_t)pb * DD + 2 * lane] = acc[j];
        if (lane == 0) { g_pm[pb] = mx[j]; g_pl[pb] = l[j]; }
    }
}

// ---------------- combine split partials (256 thr, 4-way split) ------------
__global__ __launch_bounds__(256) void k_comb(float* __restrict__ out)
{
    __shared__ float sacc[4][64];
    __shared__ float sls[4];
    int g  = blockIdx.x;                    // bh*UU + u
    int bh = g / UU;
    int t  = threadIdx.x, grp = t >> 6, d = t & 63;

    const float* pmb = g_pm + g * NSPLIT;
    float mg = -CUDART_INF_F;
#pragma unroll
    for (int i = 0; i < NSPLIT; i++) mg = fmaxf(mg, __ldg(pmb + i));

    const float* pab = g_pacc + (size_t)g * NSPLIT * DD;
    float os = 0.f, ls = 0.f;
#pragma unroll
    for (int i = 0; i < 8; i++) {
        int sp = 8 * grp + i;
        float wgt = __expf(__ldg(pmb + sp) - mg);
        os = fmaf(wgt, __ldg(pab + (size_t)sp * DD + d), os);
        ls = fmaf(wgt, __ldg(g_pl + g * NSPLIT + sp), ls);
    }
    sacc[grp][d] = os;
    if (d == 0) sls[grp] = ls;
    __syncthreads();

    if (t < 64) {
        float num = (sacc[0][t] + sacc[1][t]) + (sacc[2][t] + sacc[3][t]);
        float den = (sls[0] + sls[1]) + (sls[2] + sls[3]);
        int row = g_top[g];
        out[((size_t)bh * LQ + row) * DD + t] = num / den;
    }
}

// ---------------- launcher --------------------------------------------------
extern "C" void kernel_launch(void* const* d_in, const int* in_sizes, int n_in,
                              void* d_out, int out_size)
{
    (void)in_sizes; (void)n_in; (void)out_size;
    const float* Q   = (const float*)d_in[0];
    const float* K   = (const float*)d_in[1];
    const float* V   = (const float*)d_in[2];
    const int*   idx = (const int*)d_in[3];
    float* out = (float*)d_out;

    k_L1<<<512 + BH * LQ / 8, 256>>>(Q, K, V, idx);
    k_top<<<BH, 256>>>();
    k_L3<<<512 + NCHUNK * BH, 256>>>(Q, K, V, out);
    k_comb<<<BH * UU, 256>>>(out);
}